// round 13
// baseline (speedup 1.0000x reference)
#include <cuda_runtime.h>
#include <cuda_fp16.h>
#include <cstdint>
#include <math.h>

// ---------------------------------------------------------------------------
// Problem dims (fixed)
// ---------------------------------------------------------------------------
#define T_TOK 8192
#define H_DIM 2048
#define I_DIM 1408
#define E_NUM 32

#define SZ_HH ((size_t)T_TOK * I_DIM)

// Scratch (device globals — no allocations allowed anywhere).
__device__ __align__(256) __half g_h16[SZ_HH];   // [T][I] fp16

// ---------------------------------------------------------------------------
// PTX helpers (base-target legal: cp.async / ldmatrix / mma.sync)
// ---------------------------------------------------------------------------
__device__ __forceinline__ uint32_t smem_u32(const void* p) {
    uint32_t a;
    asm("{ .reg .u64 t; cvta.to.shared.u64 t, %1; cvt.u32.u64 %0, t; }"
        : "=r"(a) : "l"(p));
    return a;
}
__device__ __forceinline__ void cpa16(uint32_t s, const void* g) {
    asm volatile("cp.async.cg.shared.global [%0], [%1], 16;" :: "r"(s), "l"(g));
}
#define CP_COMMIT() asm volatile("cp.async.commit_group;" ::: "memory")
#define CP_WAIT1()  asm volatile("cp.async.wait_group 1;" ::: "memory")

__device__ __forceinline__ void ldsm4(uint32_t* r, uint32_t addr) {
    asm volatile("ldmatrix.sync.aligned.m8n8.x4.shared.b16 {%0,%1,%2,%3}, [%4];"
                 : "=r"(r[0]), "=r"(r[1]), "=r"(r[2]), "=r"(r[3]) : "r"(addr));
}
__device__ __forceinline__ void ldsm4t(uint32_t* r, uint32_t addr) {
    asm volatile("ldmatrix.sync.aligned.m8n8.x4.trans.shared.b16 {%0,%1,%2,%3}, [%4];"
                 : "=r"(r[0]), "=r"(r[1]), "=r"(r[2]), "=r"(r[3]) : "r"(addr));
}
__device__ __forceinline__ void mma16816(float* d, const uint32_t* a,
                                         uint32_t b0, uint32_t b1) {
    asm volatile(
        "mma.sync.aligned.m16n8k16.row.col.f32.f16.f16.f32 "
        "{%0,%1,%2,%3}, {%4,%5,%6,%7}, {%8,%9}, {%0,%1,%2,%3};"
        : "+f"(d[0]), "+f"(d[1]), "+f"(d[2]), "+f"(d[3])
        : "r"(a[0]), "r"(a[1]), "r"(a[2]), "r"(a[3]), "r"(b0), "r"(b1));
}
__device__ __forceinline__ uint32_t pkh2(float a, float b) {
    __half2 h = __floats2half2_rn(a, b);
    return *reinterpret_cast<uint32_t*>(&h);
}

// ---------------------------------------------------------------------------
// Shared tile helpers
// ---------------------------------------------------------------------------
#define APLANE 16384      // 128 x 64 fp16
#define BPLANE 16384      // 64 x 128 fp16 (two 64-n 8KB halves) — gemm2
#define BPL64  8192       // 64 x 64 fp16 — gemm1

// cp.async A prefetch (gemm2 only: A = h16 already fp16)
__device__ __forceinline__ void prefetch_a(const __half* A, int K, int k0,
                                           uint32_t st, int tid) {
    #pragma unroll
    for (int p = 0; p < 4; p++) {
        int c   = tid + 256 * p;          // 0..1023
        int row = c >> 3;                 // m 0..127
        int kc  = c & 7;
        uint32_t so = (uint32_t)(row * 128 + ((kc ^ (row & 7)) << 4));
        cpa16(st + so, A + (size_t)row * K + k0 + kc * 8);
    }
}
// ---- gemm1 A: fp32 x, one k16 quarter -> 2 float4 per thread ----
__device__ __forceinline__ void ldg_aq(const float* A, int K, int k0, int q,
                                       int tid, float4* r) {
    #pragma unroll
    for (int p = 0; p < 2; p++) {
        int c   = p * 256 + tid;             // 0..511
        int row = c >> 2;                    // m 0..127
        int ch  = c & 3;                     // 16B chunk in 64B row-quarter
        r[p] = __ldg(reinterpret_cast<const float4*>(
                     A + (size_t)row * K + k0 + q * 16 + ch * 4));
    }
}
__device__ __forceinline__ void sts_aq(const float4* r, char* dst, int tid, int q) {
    #pragma unroll
    for (int p = 0; p < 2; p++) {
        int c   = p * 256 + tid;
        int row = c >> 2;
        int ch  = c & 3;
        int kc  = 2 * q + (ch >> 1);         // 16B chunk index in 128B row
        uint32_t off = (uint32_t)(row * 128 +
                                  ((kc ^ (row & 7)) << 4) + (ch & 1) * 8);
        *reinterpret_cast<uint2*>(dst + off) =
            make_uint2(pkh2(r[p].x, r[p].y), pkh2(r[p].z, r[p].w));
    }
}
// ---- 128-wide B tile (gemm2): one k32 half -> 4 float4 per thread ----
__device__ __forceinline__ void ldg_bhalf(const float* B, int N, int k0, int n0,
                                          int tid, int h, float4* r) {
    #pragma unroll
    for (int p = 0; p < 4; p++) {
        int c   = (h * 4 + p) * 256 + tid;
        int row = c >> 5;
        int ch  = c & 31;
        r[p] = __ldg(reinterpret_cast<const float4*>(
                     B + (size_t)(k0 + row) * N + n0 + ch * 4));
    }
}
__device__ __forceinline__ void sts_bhalf(const float4* r, char* dst, int tid, int h) {
    #pragma unroll
    for (int p = 0; p < 4; p++) {
        int c   = (h * 4 + p) * 256 + tid;
        int row = c >> 5;
        int n   = (c & 31) * 4;
        int hf  = n >> 6;
        int jj  = (n & 63) >> 3;
        uint32_t off = (uint32_t)(hf * 8192 + row * 128 +
                                  ((jj ^ (row & 7)) << 4) + (n & 4) * 2);
        *reinterpret_cast<uint2*>(dst + off) =
            make_uint2(pkh2(r[p].x, r[p].y), pkh2(r[p].z, r[p].w));
    }
}
// ---- 64-wide B tile (gemm1): one k32 half -> 2 float4 per thread ----
__device__ __forceinline__ void ldg_b64h(const float* B, int N, int k0, int n0,
                                         int tid, int h, float4* r) {
    #pragma unroll
    for (int p = 0; p < 2; p++) {
        int c   = (h * 2 + p) * 256 + tid;   // 0..1023
        int row = c >> 4;                    // k 0..63
        int ch  = c & 15;                    // 16B chunk in 64-n row
        r[p] = __ldg(reinterpret_cast<const float4*>(
                     B + (size_t)(k0 + row) * N + n0 + ch * 4));
    }
}
__device__ __forceinline__ void sts_b64h(const float4* r, char* dst, int tid, int h) {
    #pragma unroll
    for (int p = 0; p < 2; p++) {
        int c   = (h * 2 + p) * 256 + tid;
        int row = c >> 4;
        int n   = (c & 15) * 4;              // 0..60
        int jj  = n >> 3;
        uint32_t off = (uint32_t)(row * 128 +
                                  ((jj ^ (row & 7)) << 4) + (n & 4) * 2);
        *reinterpret_cast<uint2*>(dst + off) =
            make_uint2(pkh2(r[p].x, r[p].y), pkh2(r[p].z, r[p].w));
    }
}
// Fragment smem offsets — verified R4-R12.
__device__ __forceinline__ uint32_t b_off(int s, int base_n, int lane) {
    int kRow = s * 16 + (lane & 7) + ((lane >> 4) << 3);
    int nOff = base_n + (((lane >> 3) & 1) << 3);
    int half = nOff >> 6;
    int jj   = (nOff & 63) >> 3;
    return (uint32_t)(half * 8192 + kRow * 128 + ((jj ^ (kRow & 7)) << 4));
}
__device__ __forceinline__ uint32_t a_off(int row, int s, int lhi) {
    int ch = 2 * s + lhi;
    return (uint32_t)(row * 128 + ((ch ^ (row & 7)) << 4));
}

// ---------------------------------------------------------------------------
// GEMM1: fused gate+up, in-register convert for BOTH operands (x fp32 and
// W fp32) — no cvt pass, no cp.async.  CTA 128x64, 2m x 4n, occ 2.
// smem: A16[2] 32K + Bg16[2] 16K + Bu16[2] 16K = 64 KB.
// A(it+1) staged in k16 quarters interleaved with the 4 MMA s-steps.
// ---------------------------------------------------------------------------
#define G1_A(s)  ((s) * APLANE)
#define G1_BG(s) (2 * APLANE + (s) * BPL64)
#define G1_BU(s) (2 * APLANE + 2 * BPL64 + (s) * BPL64)
#define G1_TOTAL (2 * APLANE + 4 * BPL64)     // 65536

__global__ __launch_bounds__(256, 2)
void gemm1_kernel(const float* __restrict__ x, const float* __restrict__ Wg,
                  const float* __restrict__ Wu, const int* __restrict__ offs)
{
    extern __shared__ char smem[];
    const uint32_t sb = smem_u32(smem);
    const int tid  = threadIdx.x;
    const int wid  = tid >> 5;
    const int lane = tid & 31;
    const int wm   = wid & 1;
    const int wn   = wid >> 1;

    const int m0 = blockIdx.y * 128;
    const int n0 = blockIdx.x * 64;
    int e = 0;
    while (offs[e] <= m0) e++;

    const float* A  = x + (size_t)m0 * H_DIM;
    const float* Bg = Wg + (size_t)e * H_DIM * I_DIM;
    const float* Bu = Wu + (size_t)e * H_DIM * I_DIM;

    float accg[4][2][4], accu[4][2][4];
    #pragma unroll
    for (int mf = 0; mf < 4; mf++)
        #pragma unroll
        for (int nf = 0; nf < 2; nf++)
            #pragma unroll
            for (int q = 0; q < 4; q++) { accg[mf][nf][q] = 0.f; accu[mf][nf][q] = 0.f; }

    // Prologue: build stage 0 for A and both B planes (register convert).
    {
        float4 ar[2], rg[2], ru[2];
        #pragma unroll
        for (int q = 0; q < 4; q++) {
            ldg_aq(A, H_DIM, 0, q, tid, ar);
            sts_aq(ar, smem + G1_A(0), tid, q);
        }
        #pragma unroll
        for (int h = 0; h < 2; h++) {
            ldg_b64h(Bg, I_DIM, 0, n0, tid, h, rg);
            ldg_b64h(Bu, I_DIM, 0, n0, tid, h, ru);
            sts_b64h(rg, smem + G1_BG(0), tid, h);
            sts_b64h(ru, smem + G1_BU(0), tid, h);
        }
    }

    const int l16 = lane & 15;
    const int lhi = lane >> 4;
    const int NIT = H_DIM / 64;   // 32

    for (int it = 0; it < NIT; it++) {
        __syncthreads();          // stage(it) stores (from it-1 / prologue) visible

        const int sp  = it & 1;
        const int spn = 1 - sp;
        const uint32_t stA = sb + G1_A(sp);
        const uint32_t bgb = sb + G1_BG(sp);
        const uint32_t bub = sb + G1_BU(sp);
        char* dA  = smem + G1_A(spn);
        char* dBg = smem + G1_BG(spn);
        char* dBu = smem + G1_BU(spn);
        const bool more = (it + 1 < NIT);
        const int k1 = (it + 1) * 64;

        float4 ar[2], rg[2], ru[2];
        if (more) {                        // issue before s0: aq0 + B h0
            ldg_aq(A, H_DIM, k1, 0, tid, ar);
            ldg_b64h(Bg, I_DIM, k1, n0, tid, 0, rg);
            ldg_b64h(Bu, I_DIM, k1, n0, tid, 0, ru);
        }

        #pragma unroll
        for (int s = 0; s < 4; s++) {
            uint32_t a[4][4], bg[4], bu[4];
            #pragma unroll
            for (int mf = 0; mf < 4; mf++)
                ldsm4(a[mf], stA + a_off(wm * 64 + mf * 16 + l16, s, lhi));
            {
                uint32_t off = b_off(s, wn * 16, lane);
                ldsm4t(bg, bgb + off);
                ldsm4t(bu, bub + off);
            }
            #pragma unroll
            for (int mf = 0; mf < 4; mf++)
                #pragma unroll
                for (int nf = 0; nf < 2; nf++) {
                    mma16816(accg[mf][nf], a[mf], bg[nf], bg[nf + 2]);
                    mma16816(accu[mf][nf], a[mf], bu[nf], bu[nf + 2]);
                }
            // staging schedule interleaved with s-steps
            if (more) {
                if (s == 0) {                       // after s0
                    sts_aq(ar, dA, tid, 0);
                    ldg_aq(A, H_DIM, k1, 1, tid, ar);
                } else if (s == 1) {                // after s1
                    sts_b64h(rg, dBg, tid, 0);
                    sts_b64h(ru, dBu, tid, 0);
                    sts_aq(ar, dA, tid, 1);
                    ldg_aq(A, H_DIM, k1, 2, tid, ar);
                    ldg_b64h(Bg, I_DIM, k1, n0, tid, 1, rg);
                    ldg_b64h(Bu, I_DIM, k1, n0, tid, 1, ru);
                } else if (s == 2) {                // after s2
                    sts_aq(ar, dA, tid, 2);
                    ldg_aq(A, H_DIM, k1, 3, tid, ar);
                } else {                            // after s3
                    sts_aq(ar, dA, tid, 3);
                    sts_b64h(rg, dBg, tid, 1);
                    sts_b64h(ru, dBu, tid, 1);
                }
            }
        }
    }

    // Epilogue: h = silu(g) * u -> fp16
    const int quad = lane >> 2, tq = lane & 3;
    #pragma unroll
    for (int mf = 0; mf < 4; mf++)
        #pragma unroll
        for (int nf = 0; nf < 2; nf++)
            #pragma unroll
            for (int h = 0; h < 2; h++) {
                int m = m0 + wm * 64 + mf * 16 + quad + h * 8;
                int n = n0 + wn * 16 + nf * 8 + tq * 2;
                float g0 = accg[mf][nf][h * 2 + 0], u0 = accu[mf][nf][h * 2 + 0];
                float g1 = accg[mf][nf][h * 2 + 1], u1 = accu[mf][nf][h * 2 + 1];
                float h0 = (g0 / (1.0f + __expf(-g0))) * u0;
                float h1 = (g1 / (1.0f + __expf(-g1))) * u1;
                *reinterpret_cast<uint32_t*>(g_h16 + (size_t)m * I_DIM + n) = pkh2(h0, h1);
            }
}

// ---------------------------------------------------------------------------
// GEMM2: down proj (unchanged R12 config: CTA 128x128, 2m x 4n, occ 2,
// triple-A single-barrier schedule, cp.async A from g_h16).
// ---------------------------------------------------------------------------
#define G2_A(s)  ((s) * APLANE)
#define G2_B(s)  (3 * APLANE + (s) * BPLANE)
#define G2_TOTAL (3 * APLANE + 2 * BPLANE)    // 81920

__global__ __launch_bounds__(256, 2)
void gemm2_kernel(const float* __restrict__ Wd, const int* __restrict__ offs,
                  float* __restrict__ out)
{
    extern __shared__ char smem[];
    const uint32_t sb = smem_u32(smem);
    const int tid  = threadIdx.x;
    const int wid  = tid >> 5;
    const int lane = tid & 31;
    const int wm   = wid & 1;          // 0..1, 64 m-rows
    const int wn   = wid >> 1;         // 0..3, 32 n-cols

    const int m0 = blockIdx.y * 128;
    const int n0 = blockIdx.x * 128;
    int e = 0;
    while (offs[e] <= m0) e++;

    const __half* A = g_h16 + (size_t)m0 * I_DIM;
    const float*  B = Wd + (size_t)e * I_DIM * H_DIM;

    float acc[4][4][4];
    #pragma unroll
    for (int mf = 0; mf < 4; mf++)
        #pragma unroll
        for (int nf = 0; nf < 4; nf++)
            #pragma unroll
            for (int q = 0; q < 4; q++) acc[mf][nf][q] = 0.f;

    prefetch_a(A, I_DIM, 0, sb + G2_A(0), tid);  CP_COMMIT();
    prefetch_a(A, I_DIM, 64, sb + G2_A(1), tid); CP_COMMIT();
    {
        float4 r[4];
        #pragma unroll
        for (int h = 0; h < 2; h++) {
            ldg_bhalf(B, H_DIM, 0, n0, tid, h, r);
            sts_bhalf(r, smem + G2_B(0), tid, h);
        }
    }

    const int l16 = lane & 15;
    const int lhi = lane >> 4;
    const int NIT = I_DIM / 64;   // 22

    for (int it = 0; it < NIT; it++) {
        CP_WAIT1();              // A(it) landed
        __syncthreads();         // orders A(it)+B16(it); frees A((it+2)%3)
        if (it + 2 < NIT)
            prefetch_a(A, I_DIM, (it + 2) * 64, sb + G2_A((it + 2) % 3), tid);
        CP_COMMIT();

        const int sp  = it & 1;
        const int spn = 1 - sp;
        const uint32_t stA = sb + G2_A(it % 3);
        const uint32_t bb  = sb + G2_B(sp);
        const bool more = (it + 1 < NIT);

        float4 r[4];
        if (more) ldg_bhalf(B, H_DIM, (it + 1) * 64, n0, tid, 0, r);

        #pragma unroll
        for (int s = 0; s < 2; s++) {
            uint32_t a[4][4], b[2][4];
            #pragma unroll
            for (int mf = 0; mf < 4; mf++)
                ldsm4(a[mf], stA + a_off(wm * 64 + mf * 16 + l16, s, lhi));
            #pragma unroll
            for (int nf2 = 0; nf2 < 2; nf2++)
                ldsm4t(b[nf2], bb + b_off(s, wn * 32 + nf2 * 16, lane));
            #pragma unroll
            for (int mf = 0; mf < 4; mf++)
                #pragma unroll
                for (int nf = 0; nf < 4; nf++) {
                    const int n2 = nf >> 1, p = nf & 1;
                    mma16816(acc[mf][nf], a[mf], b[n2][p], b[n2][p + 2]);
                }
        }

        if (more) {
            sts_bhalf(r, smem + G2_B(spn), tid, 0);
            ldg_bhalf(B, H_DIM, (it + 1) * 64, n0, tid, 1, r);
        }

        #pragma unroll
        for (int s = 2; s < 4; s++) {
            uint32_t a[4][4], b[2][4];
            #pragma unroll
            for (int mf = 0; mf < 4; mf++)
                ldsm4(a[mf], stA + a_off(wm * 64 + mf * 16 + l16, s, lhi));
            #pragma unroll
            for (int nf2 = 0; nf2 < 2; nf2++)
                ldsm4t(b[nf2], bb + b_off(s, wn * 32 + nf2 * 16, lane));
            #pragma unroll
            for (int mf = 0; mf < 4; mf++)
                #pragma unroll
                for (int nf = 0; nf < 4; nf++) {
                    const int n2 = nf >> 1, p = nf & 1;
                    mma16816(acc[mf][nf], a[mf], b[n2][p], b[n2][p + 2]);
                }
        }

        if (more) sts_bhalf(r, smem + G2_B(spn), tid, 1);
    }

    const int quad = lane >> 2, tq = lane & 3;
    #pragma unroll
    for (int mf = 0; mf < 4; mf++)
        #pragma unroll
        for (int nf = 0; nf < 4; nf++)
            #pragma unroll
            for (int h = 0; h < 2; h++) {
                int m = m0 + wm * 64 + mf * 16 + quad + h * 8;
                int n = n0 + wn * 32 + nf * 8 + tq * 2;
                *reinterpret_cast<float2*>(out + (size_t)m * H_DIM + n) =
                    make_float2(acc[mf][nf][h * 2 + 0], acc[mf][nf][h * 2 + 1]);
            }
}

// ---------------------------------------------------------------------------
extern "C" void kernel_launch(void* const* d_in, const int* in_sizes, int n_in,
                              void* d_out, int out_size)
{
    const float* x    = (const float*)d_in[0];   // [T, H]
    const float* Wg   = (const float*)d_in[1];   // [E, H, I]
    const float* Wu   = (const float*)d_in[2];   // [E, H, I]
    const float* Wd   = (const float*)d_in[3];   // [E, I, H]
    const int*   offs = (const int*)  d_in[4];   // [E]
    float*       out  = (float*)d_out;           // [T, H]

    cudaFuncSetAttribute(gemm1_kernel, cudaFuncAttributeMaxDynamicSharedMemorySize, G1_TOTAL);
    cudaFuncSetAttribute(gemm2_kernel, cudaFuncAttributeMaxDynamicSharedMemorySize, G2_TOTAL);

    // No conversion prologue at all: both GEMMs convert fp32 inputs in-register.
    gemm1_kernel<<<dim3(I_DIM / 64, T_TOK / 128), 256, G1_TOTAL>>>(x, Wg, Wu, offs);
    gemm2_kernel<<<dim3(H_DIM / 128, T_TOK / 128), 256, G2_TOTAL>>>(Wd, offs, out);
}

// round 14
// speedup vs baseline: 1.1825x; 1.1825x over previous
#include <cuda_runtime.h>
#include <cuda_fp16.h>
#include <cstdint>
#include <math.h>

// ---------------------------------------------------------------------------
// Problem dims (fixed)
// ---------------------------------------------------------------------------
#define T_TOK 8192
#define H_DIM 2048
#define I_DIM 1408
#define E_NUM 32

#define SZ_X ((size_t)T_TOK * H_DIM)
#define SZ_HH ((size_t)T_TOK * I_DIM)

// Scratch (device globals — no allocations allowed anywhere).
__device__ __align__(256) __half g_x16[SZ_X];    // [T][H] fp16
__device__ __align__(256) __half g_h16[SZ_HH];   // [T][I] fp16

// ---------------------------------------------------------------------------
// PTX helpers (base-target legal: cp.async / ldmatrix / mma.sync)
// ---------------------------------------------------------------------------
__device__ __forceinline__ uint32_t smem_u32(const void* p) {
    uint32_t a;
    asm("{ .reg .u64 t; cvta.to.shared.u64 t, %1; cvt.u32.u64 %0, t; }"
        : "=r"(a) : "l"(p));
    return a;
}
__device__ __forceinline__ void cpa16(uint32_t s, const void* g) {
    asm volatile("cp.async.cg.shared.global [%0], [%1], 16;" :: "r"(s), "l"(g));
}
#define CP_COMMIT() asm volatile("cp.async.commit_group;" ::: "memory")
#define CP_WAIT1()  asm volatile("cp.async.wait_group 1;" ::: "memory")

__device__ __forceinline__ void ldsm4(uint32_t* r, uint32_t addr) {
    asm volatile("ldmatrix.sync.aligned.m8n8.x4.shared.b16 {%0,%1,%2,%3}, [%4];"
                 : "=r"(r[0]), "=r"(r[1]), "=r"(r[2]), "=r"(r[3]) : "r"(addr));
}
__device__ __forceinline__ void ldsm4t(uint32_t* r, uint32_t addr) {
    asm volatile("ldmatrix.sync.aligned.m8n8.x4.trans.shared.b16 {%0,%1,%2,%3}, [%4];"
                 : "=r"(r[0]), "=r"(r[1]), "=r"(r[2]), "=r"(r[3]) : "r"(addr));
}
__device__ __forceinline__ void mma16816(float* d, const uint32_t* a,
                                         uint32_t b0, uint32_t b1) {
    asm volatile(
        "mma.sync.aligned.m16n8k16.row.col.f32.f16.f16.f32 "
        "{%0,%1,%2,%3}, {%4,%5,%6,%7}, {%8,%9}, {%0,%1,%2,%3};"
        : "+f"(d[0]), "+f"(d[1]), "+f"(d[2]), "+f"(d[3])
        : "r"(a[0]), "r"(a[1]), "r"(a[2]), "r"(a[3]), "r"(b0), "r"(b1));
}
__device__ __forceinline__ uint32_t pkh2(float a, float b) {
    __half2 h = __floats2half2_rn(a, b);
    return *reinterpret_cast<uint32_t*>(&h);
}

// ---------------------------------------------------------------------------
// Prologue: fp32 -> fp16 for x only.  64B per thread, two independent
// 32B load pairs for MLP (issue-bound fix: was 32B/thread @ 63% DRAM).
// Grid: SZ_X / (256*16) = 4096 blocks.
// ---------------------------------------------------------------------------
__global__ __launch_bounds__(256)
void cvt_kernel(const float* __restrict__ src, __half* __restrict__ dst)
{
    size_t base = ((size_t)blockIdx.x * 256) * 16 + threadIdx.x * 8;
    // pair 0: elements [base, base+8)
    // pair 1: elements [base + 2048, base + 2056)  (independent cache lines)
    float4 a0 = *reinterpret_cast<const float4*>(src + base);
    float4 a1 = *reinterpret_cast<const float4*>(src + base + 4);
    float4 b0 = *reinterpret_cast<const float4*>(src + base + 2048);
    float4 b1 = *reinterpret_cast<const float4*>(src + base + 2052);
    uint4 oa, ob;
    oa.x = pkh2(a0.x, a0.y);  oa.y = pkh2(a0.z, a0.w);
    oa.z = pkh2(a1.x, a1.y);  oa.w = pkh2(a1.z, a1.w);
    ob.x = pkh2(b0.x, b0.y);  ob.y = pkh2(b0.z, b0.w);
    ob.z = pkh2(b1.x, b1.y);  ob.w = pkh2(b1.z, b1.w);
    *reinterpret_cast<uint4*>(dst + base) = oa;
    *reinterpret_cast<uint4*>(dst + base + 2048) = ob;
}

// ---------------------------------------------------------------------------
// Shared tile helpers (R12, verified)
// A: fp16 [M,K] k-contig; cp.async into SW128-swizzled fp16 plane (128x64).
// B: fp32 [K,N] n-contig (native); LDG.128 -> regs -> fp16 -> STS (SW128).
// ---------------------------------------------------------------------------
#define APLANE 16384      // 128 x 64 fp16
#define BPLANE 16384      // 64 x 128 fp16 (two 64-n 8KB halves) — gemm2
#define BPL64  8192       // 64 x 64 fp16 — gemm1

__device__ __forceinline__ void prefetch_a(const __half* A, int K, int k0,
                                           uint32_t st, int tid) {
    #pragma unroll
    for (int p = 0; p < 4; p++) {
        int c   = tid + 256 * p;          // 0..1023
        int row = c >> 3;                 // m 0..127
        int kc  = c & 7;
        uint32_t so = (uint32_t)(row * 128 + ((kc ^ (row & 7)) << 4));
        cpa16(st + so, A + (size_t)row * K + k0 + kc * 8);
    }
}
// ---- 128-wide B tile (gemm2): one k32 half -> 4 float4 per thread ----
__device__ __forceinline__ void ldg_bhalf(const float* B, int N, int k0, int n0,
                                          int tid, int h, float4* r) {
    #pragma unroll
    for (int p = 0; p < 4; p++) {
        int c   = (h * 4 + p) * 256 + tid;
        int row = c >> 5;
        int ch  = c & 31;
        r[p] = __ldg(reinterpret_cast<const float4*>(
                     B + (size_t)(k0 + row) * N + n0 + ch * 4));
    }
}
__device__ __forceinline__ void sts_bhalf(const float4* r, char* dst, int tid, int h) {
    #pragma unroll
    for (int p = 0; p < 4; p++) {
        int c   = (h * 4 + p) * 256 + tid;
        int row = c >> 5;
        int n   = (c & 31) * 4;
        int hf  = n >> 6;
        int jj  = (n & 63) >> 3;
        uint32_t off = (uint32_t)(hf * 8192 + row * 128 +
                                  ((jj ^ (row & 7)) << 4) + (n & 4) * 2);
        *reinterpret_cast<uint2*>(dst + off) =
            make_uint2(pkh2(r[p].x, r[p].y), pkh2(r[p].z, r[p].w));
    }
}
// ---- 64-wide B tile (gemm1): one k32 half -> 2 float4 per thread ----
__device__ __forceinline__ void ldg_b64h(const float* B, int N, int k0, int n0,
                                         int tid, int h, float4* r) {
    #pragma unroll
    for (int p = 0; p < 2; p++) {
        int c   = (h * 2 + p) * 256 + tid;   // 0..1023
        int row = c >> 4;                    // k 0..63
        int ch  = c & 15;                    // 16B chunk in 64-n row
        r[p] = __ldg(reinterpret_cast<const float4*>(
                     B + (size_t)(k0 + row) * N + n0 + ch * 4));
    }
}
__device__ __forceinline__ void sts_b64h(const float4* r, char* dst, int tid, int h) {
    #pragma unroll
    for (int p = 0; p < 2; p++) {
        int c   = (h * 2 + p) * 256 + tid;
        int row = c >> 4;
        int n   = (c & 15) * 4;              // 0..60
        int jj  = n >> 3;
        uint32_t off = (uint32_t)(row * 128 +
                                  ((jj ^ (row & 7)) << 4) + (n & 4) * 2);
        *reinterpret_cast<uint2*>(dst + off) =
            make_uint2(pkh2(r[p].x, r[p].y), pkh2(r[p].z, r[p].w));
    }
}
// Fragment smem offsets — verified R4-R12.
__device__ __forceinline__ uint32_t b_off(int s, int base_n, int lane) {
    int kRow = s * 16 + (lane & 7) + ((lane >> 4) << 3);
    int nOff = base_n + (((lane >> 3) & 1) << 3);
    int half = nOff >> 6;
    int jj   = (nOff & 63) >> 3;
    return (uint32_t)(half * 8192 + kRow * 128 + ((jj ^ (kRow & 7)) << 4));
}
__device__ __forceinline__ uint32_t a_off(int row, int s, int lhi) {
    int ch = 2 * s + lhi;
    return (uint32_t)(row * 128 + ((ch ^ (row & 7)) << 4));
}

// ---------------------------------------------------------------------------
// GEMM1: fused gate+up (R12 best config: CTA 128x64, 2m x 4n, occ 2,
// triple-A single-barrier schedule, cp.async A from g_x16).
// ---------------------------------------------------------------------------
#define G1_A(s)  ((s) * APLANE)
#define G1_BG(s) (3 * APLANE + (s) * BPL64)
#define G1_BU(s) (3 * APLANE + 2 * BPL64 + (s) * BPL64)
#define G1_TOTAL (3 * APLANE + 4 * BPL64)     // 81920

__global__ __launch_bounds__(256, 2)
void gemm1_kernel(const float* __restrict__ Wg, const float* __restrict__ Wu,
                  const int* __restrict__ offs)
{
    extern __shared__ char smem[];
    const uint32_t sb = smem_u32(smem);
    const int tid  = threadIdx.x;
    const int wid  = tid >> 5;
    const int lane = tid & 31;
    const int wm   = wid & 1;
    const int wn   = wid >> 1;

    const int m0 = blockIdx.y * 128;
    const int n0 = blockIdx.x * 64;
    int e = 0;
    while (offs[e] <= m0) e++;

    const __half* A  = g_x16 + (size_t)m0 * H_DIM;
    const float*  Bg = Wg + (size_t)e * H_DIM * I_DIM;
    const float*  Bu = Wu + (size_t)e * H_DIM * I_DIM;

    float accg[4][2][4], accu[4][2][4];
    #pragma unroll
    for (int mf = 0; mf < 4; mf++)
        #pragma unroll
        for (int nf = 0; nf < 2; nf++)
            #pragma unroll
            for (int q = 0; q < 4; q++) { accg[mf][nf][q] = 0.f; accu[mf][nf][q] = 0.f; }

    prefetch_a(A, H_DIM, 0, sb + G1_A(0), tid);  CP_COMMIT();
    prefetch_a(A, H_DIM, 64, sb + G1_A(1), tid); CP_COMMIT();
    {
        float4 rg[2], ru[2];
        #pragma unroll
        for (int h = 0; h < 2; h++) {
            ldg_b64h(Bg, I_DIM, 0, n0, tid, h, rg);
            ldg_b64h(Bu, I_DIM, 0, n0, tid, h, ru);
            sts_b64h(rg, smem + G1_BG(0), tid, h);
            sts_b64h(ru, smem + G1_BU(0), tid, h);
        }
    }

    const int l16 = lane & 15;
    const int lhi = lane >> 4;
    const int NIT = H_DIM / 64;   // 32

    for (int it = 0; it < NIT; it++) {
        CP_WAIT1();
        __syncthreads();
        if (it + 2 < NIT)
            prefetch_a(A, H_DIM, (it + 2) * 64, sb + G1_A((it + 2) % 3), tid);
        CP_COMMIT();

        const int sp  = it & 1;
        const int spn = 1 - sp;
        const uint32_t stA = sb + G1_A(it % 3);
        const uint32_t bgb = sb + G1_BG(sp);
        const uint32_t bub = sb + G1_BU(sp);
        const bool more = (it + 1 < NIT);

        float4 rg[2], ru[2];
        if (more) {
            ldg_b64h(Bg, I_DIM, (it + 1) * 64, n0, tid, 0, rg);
            ldg_b64h(Bu, I_DIM, (it + 1) * 64, n0, tid, 0, ru);
        }

        #pragma unroll
        for (int s = 0; s < 2; s++) {
            uint32_t a[4][4], bg[4], bu[4];
            #pragma unroll
            for (int mf = 0; mf < 4; mf++)
                ldsm4(a[mf], stA + a_off(wm * 64 + mf * 16 + l16, s, lhi));
            {
                uint32_t off = b_off(s, wn * 16, lane);
                ldsm4t(bg, bgb + off);
                ldsm4t(bu, bub + off);
            }
            #pragma unroll
            for (int mf = 0; mf < 4; mf++)
                #pragma unroll
                for (int nf = 0; nf < 2; nf++) {
                    mma16816(accg[mf][nf], a[mf], bg[nf], bg[nf + 2]);
                    mma16816(accu[mf][nf], a[mf], bu[nf], bu[nf + 2]);
                }
        }

        if (more) {
            sts_b64h(rg, smem + G1_BG(spn), tid, 0);
            sts_b64h(ru, smem + G1_BU(spn), tid, 0);
            ldg_b64h(Bg, I_DIM, (it + 1) * 64, n0, tid, 1, rg);
            ldg_b64h(Bu, I_DIM, (it + 1) * 64, n0, tid, 1, ru);
        }

        #pragma unroll
        for (int s = 2; s < 4; s++) {
            uint32_t a[4][4], bg[4], bu[4];
            #pragma unroll
            for (int mf = 0; mf < 4; mf++)
                ldsm4(a[mf], stA + a_off(wm * 64 + mf * 16 + l16, s, lhi));
            {
                uint32_t off = b_off(s, wn * 16, lane);
                ldsm4t(bg, bgb + off);
                ldsm4t(bu, bub + off);
            }
            #pragma unroll
            for (int mf = 0; mf < 4; mf++)
                #pragma unroll
                for (int nf = 0; nf < 2; nf++) {
                    mma16816(accg[mf][nf], a[mf], bg[nf], bg[nf + 2]);
                    mma16816(accu[mf][nf], a[mf], bu[nf], bu[nf + 2]);
                }
        }

        if (more) {
            sts_b64h(rg, smem + G1_BG(spn), tid, 1);
            sts_b64h(ru, smem + G1_BU(spn), tid, 1);
        }
    }

    const int quad = lane >> 2, tq = lane & 3;
    #pragma unroll
    for (int mf = 0; mf < 4; mf++)
        #pragma unroll
        for (int nf = 0; nf < 2; nf++)
            #pragma unroll
            for (int h = 0; h < 2; h++) {
                int m = m0 + wm * 64 + mf * 16 + quad + h * 8;
                int n = n0 + wn * 16 + nf * 8 + tq * 2;
                float g0 = accg[mf][nf][h * 2 + 0], u0 = accu[mf][nf][h * 2 + 0];
                float g1 = accg[mf][nf][h * 2 + 1], u1 = accu[mf][nf][h * 2 + 1];
                float h0 = (g0 / (1.0f + __expf(-g0))) * u0;
                float h1 = (g1 / (1.0f + __expf(-g1))) * u1;
                *reinterpret_cast<uint32_t*>(g_h16 + (size_t)m * I_DIM + n) = pkh2(h0, h1);
            }
}

// ---------------------------------------------------------------------------
// GEMM2: down proj (R12 config: CTA 128x128, 2m x 4n, occ 2,
// triple-A single-barrier schedule, cp.async A from g_h16).
// ---------------------------------------------------------------------------
#define G2_A(s)  ((s) * APLANE)
#define G2_B(s)  (3 * APLANE + (s) * BPLANE)
#define G2_TOTAL (3 * APLANE + 2 * BPLANE)    // 81920

__global__ __launch_bounds__(256, 2)
void gemm2_kernel(const float* __restrict__ Wd, const int* __restrict__ offs,
                  float* __restrict__ out)
{
    extern __shared__ char smem[];
    const uint32_t sb = smem_u32(smem);
    const int tid  = threadIdx.x;
    const int wid  = tid >> 5;
    const int lane = tid & 31;
    const int wm   = wid & 1;          // 0..1, 64 m-rows
    const int wn   = wid >> 1;         // 0..3, 32 n-cols

    const int m0 = blockIdx.y * 128;
    const int n0 = blockIdx.x * 128;
    int e = 0;
    while (offs[e] <= m0) e++;

    const __half* A = g_h16 + (size_t)m0 * I_DIM;
    const float*  B = Wd + (size_t)e * I_DIM * H_DIM;

    float acc[4][4][4];
    #pragma unroll
    for (int mf = 0; mf < 4; mf++)
        #pragma unroll
        for (int nf = 0; nf < 4; nf++)
            #pragma unroll
            for (int q = 0; q < 4; q++) acc[mf][nf][q] = 0.f;

    prefetch_a(A, I_DIM, 0, sb + G2_A(0), tid);  CP_COMMIT();
    prefetch_a(A, I_DIM, 64, sb + G2_A(1), tid); CP_COMMIT();
    {
        float4 r[4];
        #pragma unroll
        for (int h = 0; h < 2; h++) {
            ldg_bhalf(B, H_DIM, 0, n0, tid, h, r);
            sts_bhalf(r, smem + G2_B(0), tid, h);
        }
    }

    const int l16 = lane & 15;
    const int lhi = lane >> 4;
    const int NIT = I_DIM / 64;   // 22

    for (int it = 0; it < NIT; it++) {
        CP_WAIT1();              // A(it) landed
        __syncthreads();         // orders A(it)+B16(it); frees A((it+2)%3)
        if (it + 2 < NIT)
            prefetch_a(A, I_DIM, (it + 2) * 64, sb + G2_A((it + 2) % 3), tid);
        CP_COMMIT();

        const int sp  = it & 1;
        const int spn = 1 - sp;
        const uint32_t stA = sb + G2_A(it % 3);
        const uint32_t bb  = sb + G2_B(sp);
        const bool more = (it + 1 < NIT);

        float4 r[4];
        if (more) ldg_bhalf(B, H_DIM, (it + 1) * 64, n0, tid, 0, r);

        #pragma unroll
        for (int s = 0; s < 2; s++) {
            uint32_t a[4][4], b[2][4];
            #pragma unroll
            for (int mf = 0; mf < 4; mf++)
                ldsm4(a[mf], stA + a_off(wm * 64 + mf * 16 + l16, s, lhi));
            #pragma unroll
            for (int nf2 = 0; nf2 < 2; nf2++)
                ldsm4t(b[nf2], bb + b_off(s, wn * 32 + nf2 * 16, lane));
            #pragma unroll
            for (int mf = 0; mf < 4; mf++)
                #pragma unroll
                for (int nf = 0; nf < 4; nf++) {
                    const int n2 = nf >> 1, p = nf & 1;
                    mma16816(acc[mf][nf], a[mf], b[n2][p], b[n2][p + 2]);
                }
        }

        if (more) {
            sts_bhalf(r, smem + G2_B(spn), tid, 0);
            ldg_bhalf(B, H_DIM, (it + 1) * 64, n0, tid, 1, r);
        }

        #pragma unroll
        for (int s = 2; s < 4; s++) {
            uint32_t a[4][4], b[2][4];
            #pragma unroll
            for (int mf = 0; mf < 4; mf++)
                ldsm4(a[mf], stA + a_off(wm * 64 + mf * 16 + l16, s, lhi));
            #pragma unroll
            for (int nf2 = 0; nf2 < 2; nf2++)
                ldsm4t(b[nf2], bb + b_off(s, wn * 32 + nf2 * 16, lane));
            #pragma unroll
            for (int mf = 0; mf < 4; mf++)
                #pragma unroll
                for (int nf = 0; nf < 4; nf++) {
                    const int n2 = nf >> 1, p = nf & 1;
                    mma16816(acc[mf][nf], a[mf], b[n2][p], b[n2][p + 2]);
                }
        }

        if (more) sts_bhalf(r, smem + G2_B(spn), tid, 1);
    }

    const int quad = lane >> 2, tq = lane & 3;
    #pragma unroll
    for (int mf = 0; mf < 4; mf++)
        #pragma unroll
        for (int nf = 0; nf < 4; nf++)
            #pragma unroll
            for (int h = 0; h < 2; h++) {
                int m = m0 + wm * 64 + mf * 16 + quad + h * 8;
                int n = n0 + wn * 32 + nf * 8 + tq * 2;
                *reinterpret_cast<float2*>(out + (size_t)m * H_DIM + n) =
                    make_float2(acc[mf][nf][h * 2 + 0], acc[mf][nf][h * 2 + 1]);
            }
}

// ---------------------------------------------------------------------------
extern "C" void kernel_launch(void* const* d_in, const int* in_sizes, int n_in,
                              void* d_out, int out_size)
{
    const float* x    = (const float*)d_in[0];   // [T, H]
    const float* Wg   = (const float*)d_in[1];   // [E, H, I]
    const float* Wu   = (const float*)d_in[2];   // [E, H, I]
    const float* Wd   = (const float*)d_in[3];   // [E, I, H]
    const int*   offs = (const int*)  d_in[4];   // [E]
    float*       out  = (float*)d_out;           // [T, H]

    __half* x16;
    cudaGetSymbolAddress((void**)&x16, g_x16);

    cudaFuncSetAttribute(gemm1_kernel, cudaFuncAttributeMaxDynamicSharedMemorySize, G1_TOTAL);
    cudaFuncSetAttribute(gemm2_kernel, cudaFuncAttributeMaxDynamicSharedMemorySize, G2_TOTAL);

    cvt_kernel<<<(int)(SZ_X / 4096), 256>>>(x, x16);

    gemm1_kernel<<<dim3(I_DIM / 64, T_TOK / 128), 256, G1_TOTAL>>>(Wg, Wu, offs);
    gemm2_kernel<<<dim3(H_DIM / 128, T_TOK / 128), 256, G2_TOTAL>>>(Wd, offs, out);
}